// round 17
// baseline (speedup 1.0000x reference)
#include <cuda_runtime.h>
#include <cuda_bf16.h>
#include <cstdint>

#define BB 2
#define SS 2048
#define HH 1024
#define NH 16
#define HD 64
#define MM (BB*SS)   // 4096 rows

// Scratch (allocation is forbidden; use __device__ globals)
__device__ uint32_t g_xTF[(size_t)MM*HH];         // x as tf32
__device__ uint32_t g_xHL[(size_t)MM*HH];         // x bf16 hi/lo, quad-permuted per 8-pair group
__device__ uint32_t g_WdT[(size_t)HH*1024];       // (Wq-Wk)^T [n][k-pairs hi/lo, quad-permuted]
__device__ uint32_t g_WvTF[(size_t)HH*HH];        // Wv as tf32
__device__ uint32_t g_WoTF[(size_t)HH*HH];        // Wo as tf32
__device__ float    g_bd[HH];
__device__ uint32_t g_DHL[(size_t)MM*HH];         // D, bf16 hi/lo, quad-permuted per head
__device__ uint32_t g_VtP[(size_t)BB*NH*HD*SS];   // V^T tf32, keys in PHI order, per (b,h)
__device__ uint32_t g_C[(size_t)MM*HH];           // ctx as tf32

__device__ __forceinline__ uint32_t f2tf32(float x) {
    uint32_t r;
    asm("cvt.rna.tf32.f32 %0, %1;" : "=r"(r) : "f"(x));
    return r;
}
__device__ __forceinline__ uint32_t bfpack(float x0, float x1) {
    __nv_bfloat162 t;
    t.x = __float2bfloat16_rn(x0);
    t.y = __float2bfloat16_rn(x1);
    return *(uint32_t*)&t;
}
__device__ __forceinline__ void bfsplit2(float x0, float x1, uint32_t& hi, uint32_t& lo) {
    __nv_bfloat16 h0 = __float2bfloat16_rn(x0), h1 = __float2bfloat16_rn(x1);
    float r0 = x0 - __bfloat162float(h0), r1 = x1 - __bfloat162float(h1);
    __nv_bfloat162 th; th.x = h0; th.y = h1;
    hi = *(uint32_t*)&th;
    lo = bfpack(r0, r1);
}
__device__ __forceinline__ void mma8(float* c,
                                     uint32_t a0, uint32_t a1, uint32_t a2, uint32_t a3,
                                     uint32_t b0, uint32_t b1) {
    asm volatile(
        "mma.sync.aligned.m16n8k8.row.col.f32.tf32.tf32.f32 "
        "{%0,%1,%2,%3}, {%4,%5,%6,%7}, {%8,%9}, {%0,%1,%2,%3};"
        : "+f"(c[0]), "+f"(c[1]), "+f"(c[2]), "+f"(c[3])
        : "r"(a0), "r"(a1), "r"(a2), "r"(a3), "r"(b0), "r"(b1));
}
__device__ __forceinline__ void mma16(float* c,
                                      uint32_t a0, uint32_t a1, uint32_t a2, uint32_t a3,
                                      uint32_t b0, uint32_t b1) {
    asm volatile(
        "mma.sync.aligned.m16n8k16.row.col.f32.bf16.bf16.f32 "
        "{%0,%1,%2,%3}, {%4,%5,%6,%7}, {%8,%9}, {%0,%1,%2,%3};"
        : "+f"(c[0]), "+f"(c[1]), "+f"(c[2]), "+f"(c[3])
        : "r"(a0), "r"(a1), "r"(a2), "r"(a3), "r"(b0), "r"(b1));
}
__device__ __forceinline__ uint32_t smem_u32(const void* p) {
    uint32_t a;
    asm("{ .reg .u64 t; cvta.to.shared.u64 t, %1; cvt.u32.u64 %0, t; }" : "=r"(a) : "l"(p));
    return a;
}
__device__ __forceinline__ void cp16(uint32_t dst, const void* src) {
    asm volatile("cp.async.ca.shared.global [%0], [%1], 16;" :: "r"(dst), "l"(src));
}
__device__ __forceinline__ void cp_commit() { asm volatile("cp.async.commit_group;"); }
template<int N> __device__ __forceinline__ void cp_wait() {
    asm volatile("cp.async.wait_group %0;" :: "n"(N));
}

// ---------------------------------------------------------------------------
// Fused prep: one launch, block-range dispatch.
// blocks [0,4096):   x -> tf32 + quad-permuted bf16 hi/lo (+ bd)
// blocks [4096,5120): Wv -> tf32
// blocks [5120,6144): Wo -> tf32
// blocks [6144,7168): (Wq-Wk)^T quad-permuted bf16 hi/lo
// ---------------------------------------------------------------------------
__global__ __launch_bounds__(256) void prep_all(const float* __restrict__ x,
                                                const float* __restrict__ Wq,
                                                const float* __restrict__ bq,
                                                const float* __restrict__ Wk,
                                                const float* __restrict__ bk,
                                                const float* __restrict__ Wv,
                                                const float* __restrict__ Wo,
                                                uint32_t* __restrict__ dWv,
                                                uint32_t* __restrict__ dWo) {
    __shared__ float t[32][33];
    int bid = blockIdx.x, tid = threadIdx.x;
    if (bid < 4096) {
        int i = bid * 256 + tid;                     // over MM*HH/4
        float4 v = ((const float4*)x)[i];
        ((uint4*)g_xTF)[i] = make_uint4(f2tf32(v.x), f2tf32(v.y), f2tf32(v.z), f2tf32(v.w));
        uint32_t h0, l0, h1, l1;
        bfsplit2(v.x, v.y, h0, l0);
        bfsplit2(v.z, v.w, h1, l1);
        int P = 2 * i;
        size_t base = (size_t)(P >> 3) * 16;
        int p0 = P & 7, p1 = p0 + 1;
        *(uint2*)&g_xHL[base + 4 * (p0 & 3) + 2 * ((p0 >> 2) & 1)] = make_uint2(h0, l0);
        *(uint2*)&g_xHL[base + 4 * (p1 & 3) + 2 * ((p1 >> 2) & 1)] = make_uint2(h1, l1);
        if (i < HH) g_bd[i] = bq[i] - bk[i];
    } else if (bid < 6144) {
        const float* src = (bid < 5120) ? Wv : Wo;
        uint32_t* dst = (bid < 5120) ? dWv : dWo;
        int i = (bid - ((bid < 5120) ? 4096 : 5120)) * 256 + tid;   // over HH*HH/4
        float4 v = ((const float4*)src)[i];
        ((uint4*)dst)[i] = make_uint4(f2tf32(v.x), f2tf32(v.y), f2tf32(v.z), f2tf32(v.w));
    } else {
        int b2 = bid - 6144;                         // 0..1023
        int k0 = (b2 & 31) * 32, n0 = (b2 >> 5) * 32;
        int tn = tid & 31, tk = tid >> 5;
        #pragma unroll
        for (int i = 0; i < 4; i++) {
            int k = tk + i * 8;
            size_t idx = (size_t)(k0 + k) * HH + n0 + tn;
            t[k][tn] = Wq[idx] - Wk[idx];
        }
        __syncthreads();
        #pragma unroll
        for (int i = 0; i < 2; i++) {
            int idx = tid + i * 256;
            int n = idx >> 4, kp = idx & 15;
            int P = (k0 >> 1) + kp;
            int p = P & 7;
            uint32_t h, l;
            bfsplit2(t[2 * kp][n], t[2 * kp + 1][n], h, l);
            size_t dst = (size_t)(n0 + n) * 1024 + (size_t)(P >> 3) * 16
                       + 4 * (p & 3) + 2 * ((p >> 2) & 1);
            *(uint2*)&g_WdT[dst] = make_uint2(h, l);
        }
    }
}

// ---------------------------------------------------------------------------
// FUSED D+V projection: grid (8, 32, 2).
// z=0: D = x @ Wd + bd, 3xBF16 all-LDS.128 path (R16-proven, bit-identical)
//      -> g_DHL quad-permuted.
// z=1: V = x @ Wv + bv, tf32 path (R11-proven, bit-identical)
//      -> g_VtP transposed, PHI keys.
// 512 CTAs pack the 2-CTA/SM residency slots continuously (no inter-kernel
// gap, no idle slots, cross-workload tail overlap). Dynamic smem 64KB.
// ---------------------------------------------------------------------------
__global__ __launch_bounds__(256, 2) void gemm_dv(const uint32_t* __restrict__ AHL,
                                                  const uint32_t* __restrict__ WT,
                                                  const float* __restrict__ biasD,
                                                  uint32_t* __restrict__ Dout,
                                                  const uint32_t* __restrict__ ATF,
                                                  const uint32_t* __restrict__ WV,
                                                  const float* __restrict__ biasV,
                                                  uint32_t* __restrict__ Vout) {
    extern __shared__ uint32_t sm[];
    int tid = threadIdx.x, lane = tid & 31, w = tid >> 5;
    int la3 = lane & 3, l4 = lane >> 2;
    int row0 = blockIdx.y * 128, col0 = blockIdx.x * 128;
    uint32_t smb = smem_u32(sm);

    if (blockIdx.z == 0) {
        // ---------------- D path: 3xBF16, all-LDS.128 ----------------
        const int ASZ = 128 * 32, STG = 2 * ASZ;
        int wm = (w & 1) * 64, wn = (w >> 1) * 32;
        float acc[4][4][4] = {};

        #define B_FILL(T) do {                                                   \
            int u0 = (T) * 32, bf = (T) & 1;                                     \
            uint32_t ab = smb + bf * STG * 4;                                    \
            uint32_t bb2 = ab + ASZ * 4;                                         \
            _Pragma("unroll")                                                    \
            for (int i = 0; i < 4; i++) {                                        \
                int c = tid + i * 256;                                           \
                int r = c >> 3, j = c & 7;                                       \
                uint32_t off = (r * 32 + ((4 * j) ^ ((r & 1) << 4))) * 4;        \
                cp16(ab + off,  AHL + (size_t)(row0 + r) * 1024 + u0 + 4 * j);   \
                cp16(bb2 + off, WT  + (size_t)(col0 + r) * 1024 + u0 + 4 * j);   \
            }                                                                    \
        } while (0)

        B_FILL(0); cp_commit();

        for (int t = 0; t < HH / 32; t++) {
            if (t + 1 < HH / 32) { B_FILL(t + 1); cp_commit(); cp_wait<1>(); }
            else                 { cp_wait<0>(); }
            __syncthreads();
            const uint32_t* Ab = sm + (t & 1) * STG;
            const uint32_t* Bb = Ab + ASZ;
            int sx = (l4 & 1) << 4;

            #pragma unroll
            for (int ks = 0; ks < 2; ks++) {
                int g = (ks * 16 + 4 * la3) ^ sx;
                uint4 Bq[4];
                #pragma unroll
                for (int nt = 0; nt < 4; nt++)
                    Bq[nt] = *(const uint4*)&Bb[(wn + nt * 8 + l4) * 32 + g];
                #pragma unroll
                for (int mt = 0; mt < 4; mt++) {
                    int m = wm + mt * 16 + l4;
                    uint4 Aq0 = *(const uint4*)&Ab[m       * 32 + g];
                    uint4 Aq8 = *(const uint4*)&Ab[(m + 8) * 32 + g];
                    #pragma unroll
                    for (int nt = 0; nt < 4; nt++) {
                        mma16(acc[mt][nt], Aq0.x, Aq8.x, Aq0.z, Aq8.z, Bq[nt].x, Bq[nt].z);
                        mma16(acc[mt][nt], Aq0.x, Aq8.x, Aq0.z, Aq8.z, Bq[nt].y, Bq[nt].w);
                        mma16(acc[mt][nt], Aq0.y, Aq8.y, Aq0.w, Aq8.w, Bq[nt].x, Bq[nt].z);
                    }
                }
            }
            __syncthreads();
        }
        #undef B_FILL

        #pragma unroll
        for (int mt = 0; mt < 4; mt++) {
            int r = row0 + wm + mt * 16 + l4;
            #pragma unroll
            for (int nt = 0; nt < 4; nt++) {
                int cb = col0 + wn + nt * 8 + 2 * la3;
                int p = cb >> 1;
                int head = p >> 5, q = p & 31;
                int off = head * 64 + 16 * (q >> 3) + 4 * (q & 3) + 2 * ((q >> 2) & 1);
                float v0 = acc[mt][nt][0] + biasD[cb];
                float v1 = acc[mt][nt][1] + biasD[cb + 1];
                float v2 = acc[mt][nt][2] + biasD[cb];
                float v3 = acc[mt][nt][3] + biasD[cb + 1];
                uint32_t h, l;
                bfsplit2(v0, v1, h, l);
                *(uint2*)&Dout[(size_t)r * HH + off] = make_uint2(h, l);
                bfsplit2(v2, v3, h, l);
                *(uint2*)&Dout[(size_t)(r + 8) * HH + off] = make_uint2(h, l);
            }
        }
    } else {
        // ---------------- V path: tf32, MODE 3 (transposed PHI out) ----------
        const int ASZ = 128 * 20, BSZ = 16 * 136;
        int wm = (w & 1) * 64, wn = (w >> 1) * 32;
        uint32_t asb = smb, bsb = smb + 2 * ASZ * 4;
        float acc[4][4][4] = {};

        #define G_FILL(T) do {                                                   \
            int k0 = (T) * 16, bf = (T) & 1;                                     \
            _Pragma("unroll")                                                    \
            for (int i = 0; i < 2; i++) {                                        \
                int f = tid + i * 256;                                           \
                int r = f >> 2, j = f & 3;                                       \
                cp16(asb + (bf * ASZ + r * 20 + 4 * j) * 4,                      \
                     ATF + (size_t)(row0 + r) * HH + k0 + 4 * j);                \
            }                                                                    \
            _Pragma("unroll")                                                    \
            for (int i = 0; i < 2; i++) {                                        \
                int f = tid + i * 256;                                           \
                int r = f >> 5, j = f & 31;                                      \
                cp16(bsb + (bf * BSZ + r * 136 + 4 * j) * 4,                     \
                     WV + (size_t)(k0 + r) * HH + col0 + 4 * j);                 \
            }                                                                    \
        } while (0)

        G_FILL(0); cp_commit();

        for (int t = 0; t < HH / 16; t++) {
            if (t + 1 < HH / 16) { G_FILL(t + 1); cp_commit(); cp_wait<1>(); }
            else                 { cp_wait<0>(); }
            __syncthreads();
            const uint32_t* Ab = sm + (t & 1) * ASZ;
            const uint32_t* Bb = sm + 2 * ASZ + (t & 1) * BSZ;

            #pragma unroll
            for (int kk = 0; kk < 16; kk += 8) {
                int rc = (kk + la3) * 136, rd = (kk + 4 + la3) * 136;
                uint32_t bf2[4][2];
                #pragma unroll
                for (int nt = 0; nt < 4; nt++) {
                    int n = wn + nt * 8 + l4;
                    bf2[nt][0] = Bb[rc + n];
                    bf2[nt][1] = Bb[rd + n];
                }
                #pragma unroll
                for (int mt = 0; mt < 4; mt++) {
                    int m = wm + mt * 16 + l4;
                    uint32_t a0 = Ab[m * 20 + kk + la3];
                    uint32_t a1 = Ab[(m + 8) * 20 + kk + la3];
                    uint32_t a2 = Ab[m * 20 + kk + 4 + la3];
                    uint32_t a3 = Ab[(m + 8) * 20 + kk + 4 + la3];
                    #pragma unroll
                    for (int nt = 0; nt < 4; nt++)
                        mma8(acc[mt][nt], a0, a1, a2, a3, bf2[nt][0], bf2[nt][1]);
                }
            }
            __syncthreads();
        }
        #undef G_FILL

        #pragma unroll
        for (int mt = 0; mt < 4; mt++) {
            int r = row0 + wm + mt * 16 + l4;
            #pragma unroll
            for (int nt = 0; nt < 4; nt++) {
                int cb = col0 + wn + nt * 8 + 2 * la3;
                float v0 = acc[mt][nt][0] + biasV[cb];
                float v1 = acc[mt][nt][1] + biasV[cb + 1];
                float v2 = acc[mt][nt][2] + biasV[cb];
                float v3 = acc[mt][nt][3] + biasV[cb + 1];
                int bI = r >> 11, s = r & 2047;
                int hI = cb >> 6, d = cb & 63;
                int pos = 16 * (s >> 4) + 4 * ((s >> 1) & 3) + 2 * ((s >> 3) & 1) + (s & 1);
                size_t hb = (size_t)(bI * NH + hI) * HD;
                Vout[(hb + d)     * SS + pos    ] = f2tf32(v0);
                Vout[(hb + d + 1) * SS + pos    ] = f2tf32(v1);
                Vout[(hb + d)     * SS + pos + 2] = f2tf32(v2);
                Vout[(hb + d + 1) * SS + pos + 2] = f2tf32(v3);
            }
        }
    }
}

// ---------------------------------------------------------------------------
// tf32 GEMM for O-projection (R11-proven, MODE 0 only).
// ---------------------------------------------------------------------------
__global__ __launch_bounds__(256, 2) void gemm_o(const uint32_t* __restrict__ A,
                                                 const uint32_t* __restrict__ W,
                                                 const float* __restrict__ bias,
                                                 float* __restrict__ Cout) {
    const int ASZ = 128 * 20, BSZ = 16 * 136;
    __shared__ uint32_t As[2 * ASZ];
    __shared__ uint32_t Bs[2 * BSZ];
    int tid = threadIdx.x, lane = tid & 31, w = tid >> 5;
    int la3 = lane & 3, l4 = lane >> 2;
    int wm = (w & 1) * 64, wn = (w >> 1) * 32;
    int row0 = blockIdx.y * 128, col0 = blockIdx.x * 128;

    uint32_t asb = smem_u32(As), bsb = smem_u32(Bs);
    float acc[4][4][4] = {};

    #define G_FILL(T) do {                                                       \
        int k0 = (T) * 16, bf = (T) & 1;                                         \
        _Pragma("unroll")                                                        \
        for (int i = 0; i < 2; i++) {                                            \
            int f = tid + i * 256;                                               \
            int r = f >> 2, j = f & 3;                                           \
            cp16(asb + (bf * ASZ + r * 20 + 4 * j) * 4,                          \
                 A + (size_t)(row0 + r) * HH + k0 + 4 * j);                      \
        }                                                                        \
        _Pragma("unroll")                                                        \
        for (int i = 0; i < 2; i++) {                                            \
            int f = tid + i * 256;                                               \
            int r = f >> 5, j = f & 31;                                          \
            cp16(bsb + (bf * BSZ + r * 136 + 4 * j) * 4,                         \
                 W + (size_t)(k0 + r) * HH + col0 + 4 * j);                      \
        }                                                                        \
    } while (0)

    G_FILL(0); cp_commit();

    for (int t = 0; t < HH / 16; t++) {
        if (t + 1 < HH / 16) { G_FILL(t + 1); cp_commit(); cp_wait<1>(); }
        else                 { cp_wait<0>(); }
        __syncthreads();
        const uint32_t* Ab = As + (t & 1) * ASZ;
        const uint32_t* Bb = Bs + (t & 1) * BSZ;

        #pragma unroll
        for (int kk = 0; kk < 16; kk += 8) {
            int rc = (kk + la3) * 136, rd = (kk + 4 + la3) * 136;
            uint32_t bf[4][2];
            #pragma unroll
            for (int nt = 0; nt < 4; nt++) {
                int n = wn + nt * 8 + l4;
                bf[nt][0] = Bb[rc + n];
                bf[nt][1] = Bb[rd + n];
            }
            #pragma unroll
            for (int mt = 0; mt < 4; mt++) {
                int m = wm + mt * 16 + l4;
                uint32_t a0 = Ab[m * 20 + kk + la3];
                uint32_t a1 = Ab[(m + 8) * 20 + kk + la3];
                uint32_t a2 = Ab[m * 20 + kk + 4 + la3];
                uint32_t a3 = Ab[(m + 8) * 20 + kk + 4 + la3];
                #pragma unroll
                for (int nt = 0; nt < 4; nt++)
                    mma8(acc[mt][nt], a0, a1, a2, a3, bf[nt][0], bf[nt][1]);
            }
        }
        __syncthreads();
    }
    #undef G_FILL

    #pragma unroll
    for (int mt = 0; mt < 4; mt++) {
        int r = row0 + wm + mt * 16 + l4;
        #pragma unroll
        for (int nt = 0; nt < 4; nt++) {
            int cb = col0 + wn + nt * 8 + 2 * la3;
            Cout[(size_t)r       * HH + cb    ] = acc[mt][nt][0] + bias[cb];
            Cout[(size_t)r       * HH + cb + 1] = acc[mt][nt][1] + bias[cb + 1];
            Cout[(size_t)(r + 8) * HH + cb    ] = acc[mt][nt][2] + bias[cb];
            Cout[(size_t)(r + 8) * HH + cb + 1] = acc[mt][nt][3] + bias[cb + 1];
        }
    }
}

// ---------------------------------------------------------------------------
// Fused anti-causal gaussian attention. QK 3xBF16, PV tf32. (R11-proven)
// ---------------------------------------------------------------------------
__global__ __launch_bounds__(128, 4) void attn_tc(const uint32_t* __restrict__ DH,
                                                  const uint32_t* __restrict__ VtP,
                                                  uint32_t* __restrict__ C) {
    extern __shared__ uint32_t sm[];
    const int DK0 = 0;                 // [64][64] bf16 pairs, quad-permuted
    const int VT0 = 64 * 64;           // [64][64] tf32, PHI keys
    const int PS0 = VT0 + 64 * 64;     // [64][64] tf32, PHI keys

    int tid = threadIdx.x, lane = tid & 31, w = tid >> 5;
    int la3 = lane & 3, l4 = lane >> 2;
    int h = blockIdx.x, b = blockIdx.y, q0 = blockIdx.z * 64;
    const uint32_t* DHb = DH + (size_t)b * SS * HH + h * 64;
    const uint32_t* Vb  = VtP + (size_t)(b * NH + h) * HD * SS;
    int qrow = w * 16 + l4;
    int sw = (l4 & 1) << 4;

    uint32_t smb = smem_u32(sm);
    uint32_t dkb = smb + DK0 * 4;
    uint32_t vtb = smb + VT0 * 4;

    uint32_t aH[4][4], aL[4][4];
    {
        const uint32_t* r0 = DHb + (size_t)(q0 + qrow) * HH;
        const uint32_t* r8 = r0 + (size_t)8 * HH;
        #pragma unroll
        for (int K = 0; K < 4; K++) {
            uint4 Q0 = *(const uint4*)&r0[16 * K + 4 * la3];
            uint4 Q8 = *(const uint4*)&r8[16 * K + 4 * la3];
            aH[K][0] = Q0.x; aL[K][0] = Q0.y; aH[K][2] = Q0.z; aL[K][2] = Q0.w;
            aH[K][1] = Q8.x; aL[K][1] = Q8.y; aH[K][3] = Q8.z; aL[K][3] = Q8.w;
        }
    }

    float ctx[8][4] = {};
    int nT = (SS - q0) / 64;

    #define FILL_DK(T) do {                                                      \
        int k0t = q0 + (T) * 64;                                                 \
        _Pragma("unroll")                                                        \
        for (int i = 0; i < 8; i++) {                                            \
            int idx = tid + i * 128;                                             \
            int r = idx >> 4, j = idx & 15;                                      \
            cp16(dkb + (r * 64 + ((4 * j) ^ ((r & 1) << 4))) * 4,                \
                 DHb + (size_t)(k0t + r) * HH + 4 * j);                          \
        }                                                                        \
    } while (0)
    #define FILL_V(T) do {                                                       \
        int k0t = q0 + (T) * 64;                                                 \
        _Pragma("unroll")                                                        \
        for (int i = 0; i < 8; i++) {                                            \
            int idx = tid + i * 128;                                             \
            int d = idx >> 4, j = idx & 15;                                      \
            cp16(vtb + (d * 64 + ((4 * j) ^ ((d & 1) << 4))) * 4,                \
                 Vb + (size_t)d * SS + k0t + 4 * j);                             \
        }                                                                        \
    } while (0)

    FILL_DK(0); cp_commit();
    FILL_V(0);  cp_commit();

    for (int t = 0; t < nT; t++) {
        int k0 = q0 + t * 64;
        cp_wait<1>();          // Dk(t) resident
        __syncthreads();

        const uint32_t* Dk = sm + DK0;
        const uint32_t* Vp = sm + VT0;
        uint32_t* Pw = sm + PS0;

        // ---- QK: S[16q x 64k] per warp, 3xBF16 over d=64 (all LDS.128) ----
        float s4[8][4] = {};
        #pragma unroll
        for (int K = 0; K < 4; K++) {
            #pragma unroll
            for (int nt = 0; nt < 8; nt++) {
                const uint32_t* br = Dk + (nt * 8 + l4) * 64;
                uint4 Dq = *(const uint4*)&br[(16 * K + 4 * la3) ^ sw];
                mma16(s4[nt], aH[K][0], aH[K][1], aH[K][2], aH[K][3], Dq.x, Dq.z);
                mma16(s4[nt], aH[K][0], aH[K][1], aH[K][2], aH[K][3], Dq.y, Dq.w);
                mma16(s4[nt], aL[K][0], aL[K][1], aL[K][2], aL[K][3], Dq.x, Dq.z);
            }
        }

        __syncthreads();                       // all warps done reading Dk
        if (t + 1 < nT) FILL_DK(t + 1);        // overlaps mask + PV
        cp_commit();

        // ---- mask (k > q strictly) + exp -> Ps (PHI layout, STS.128) ----
        #pragma unroll
        for (int kt2 = 0; kt2 < 4; kt2++) {
            int nt0 = 2 * kt2, nt1 = nt0 + 1;
            int kg0 = k0 + nt0 * 8 + 2 * la3;
            int kg1 = k0 + nt1 * 8 + 2 * la3;
            int qa = q0 + qrow, qb8 = qa + 8;
            float e0 = (kg0     > qa) ? __expf(-0.5f * s4[nt0][0]) : 0.0f;
            float e1 = (kg0 + 1 > qa) ? __expf(-0.5f * s4[nt0][1]) : 0.0f;
            float e2 = (kg1     > qa) ? __expf(-0.5f * s4[nt1][0]) : 0.0f;
            float e3 = (kg1 + 1 > qa) ? __expf(-0.5f * s4[nt1][1]) : 0.0f;
            *(uint4*)&Pw[qrow * 64 + ((16 * kt2 + 4 * la3) ^ sw)] =
                make_uint4(f2tf32(e0), f2tf32(e1), f2tf32(e2), f2tf32(e3));
            e0 = (kg0     > qb8) ? __expf(-0.5f * s4[nt0][2]) : 0.0f;
            e1 = (kg0 + 1 > qb8) ? __expf(-0.5f * s4[nt0][3]) : 0.0f;
            e2 = (kg1     > qb8) ? __expf(-0.5f * s4[nt1][2]) : 0.0f;
            e3 = (kg1 + 1 > qb8) ? __expf(-0.5f * s4[nt1][3]) : 0.0f;
            *(uint4*)&Pw[(qrow + 8) * 64 + ((16 * kt2 + 4 * la3) ^ sw)] =
                make_uint4(f2tf32(e0), f2tf32(e1), f2tf32(e2), f2tf32(e3));
        }
        __syncwarp();   // Pw rows are warp-private

        cp_wait<1>();          // V(t) resident
        __syncthreads();

        // ---- PV: ctx += P @ V over 64 keys (all LDS.128) ----
        #pragma unroll
        for (int kt2 = 0; kt2 < 4; kt2++) {
            uint4 Pa = *(const uint4*)&Pw[qrow * 64 + ((16 * kt2 + 4 * la3) ^ sw)];
            uint4 Pb = *(const uint4*)&Pw[(qrow + 8) * 64 + ((16 * kt2 + 4 * la3) ^ sw)];
            #pragma unroll
            for (int nt = 0; nt < 8; nt++) {
                int vr = nt * 8 + l4;
                uint4 Vq = *(const uint4*)&Vp[vr * 64 + ((16 * kt2 + 4 * la3) ^ ((vr & 1) << 4))];
                mma8(ctx[nt], Pa.x, Pb.x, Pa.y, Pb.y, Vq.x, Vq.y);
                mma8(ctx[nt], Pa.z, Pb.z, Pa.w, Pb.w, Vq.z, Vq.w);
            }
        }

        __syncthreads();                       // all warps done reading Vp/Ps
        if (t + 1 < nT) FILL_V(t + 1);         // overlaps next QK
        cp_commit();
    }

    // Store ctx as tf32 in merged [B,S,H] layout
    uint32_t* Cb = C + (size_t)b * SS * HH + h * HD;
    #pragma unroll
    for (int nt = 0; nt < 8; nt++) {
        int r = q0 + qrow;
        int c = nt * 8 + 2 * la3;
        *(uint2*)&Cb[(size_t)r       * HH + c] = make_uint2(f2tf32(ctx[nt][0]), f2tf32(ctx[nt][1]));
        *(uint2*)&Cb[(size_t)(r + 8) * HH + c] = make_uint2(f2tf32(ctx[nt][2]), f2tf32(ctx[nt][3]));
    }
    #undef FILL_DK
    #undef FILL_V
}

static const int ATTN_SMEM = (3 * 64 * 64) * 4;       // 49152 B
static const int DV_SMEM   = (2 * 2 * 128 * 32) * 4;  // 65536 B

extern "C" void kernel_launch(void* const* d_in, const int* in_sizes, int n_in,
                              void* d_out, int out_size) {
    const float* x  = (const float*)d_in[0];
    const float* Wq = (const float*)d_in[1];
    const float* bq = (const float*)d_in[2];
    const float* Wk = (const float*)d_in[3];
    const float* bk = (const float*)d_in[4];
    const float* Wv = (const float*)d_in[5];
    const float* bv = (const float*)d_in[6];
    const float* Wo = (const float*)d_in[7];
    const float* bo = (const float*)d_in[8];
    float* out = (float*)d_out;

    uint32_t *pxTF, *pxHL, *pWdT, *pWvTF, *pWoTF, *pDHL, *pVtP, *pC;
    float *pbd;
    cudaGetSymbolAddress((void**)&pxTF,  g_xTF);
    cudaGetSymbolAddress((void**)&pxHL,  g_xHL);
    cudaGetSymbolAddress((void**)&pWdT,  g_WdT);
    cudaGetSymbolAddress((void**)&pWvTF, g_WvTF);
    cudaGetSymbolAddress((void**)&pWoTF, g_WoTF);
    cudaGetSymbolAddress((void**)&pbd,   g_bd);
    cudaGetSymbolAddress((void**)&pDHL,  g_DHL);
    cudaGetSymbolAddress((void**)&pVtP,  g_VtP);
    cudaGetSymbolAddress((void**)&pC,    g_C);

    static bool attr_set = false;
    if (!attr_set) {
        cudaFuncSetAttribute(attn_tc, cudaFuncAttributeMaxDynamicSharedMemorySize, ATTN_SMEM);
        cudaFuncSetAttribute(gemm_dv, cudaFuncAttributeMaxDynamicSharedMemorySize, DV_SMEM);
        attr_set = true;
    }

    // 1. fused prep (x formats, Wd^T split, Wv/Wo tf32, bd)
    prep_all<<<7168, 256>>>(x, Wq, bq, Wk, bk, Wv, Wo, pWvTF, pWoTF);

    // 2. fused D + V projections (z=0: bf16x3 D, z=1: tf32 V)
    gemm_dv<<<dim3(HH / 128, MM / 128, 2), 256, DV_SMEM>>>(
        pxHL, pWdT, pbd, pDHL, pxTF, pWvTF, bv, pVtP);

    // 3. fused attention (LPT: qb slowest-varying, longest first)
    dim3 agrid(NH, BB, SS / 64);
    attn_tc<<<agrid, 128, ATTN_SMEM>>>(pDHL, pVtP, pC);

    // 4. out = ctx @ Wo + bo (tf32)
    gemm_o<<<dim3(HH / 128, MM / 128), 256>>>(pC, pWoTF, bo, out);
}